// round 1
// baseline (speedup 1.0000x reference)
#include <cuda_runtime.h>
#include <math.h>

#define Bb 32
#define Ss 256
#define Vv 10000
#define Ee 512
#define Hh 1024
#define Ll 3

// ---------------- scratch (static __device__ arrays; no allocation) ----------------
__device__ float g_fp[Bb * Ss];                  // layer-normed fix_pred, [B,S]
__device__ float g_inputx[Ss * Bb * Hh];         // input projection, [S,B,H]
__device__ float g_inp[Ss * Bb * Hh];            // gated layer input,  [S,B,H]
__device__ float g_x[Ss * Bb * Hh];              // layer output / h history, [S,B,H]
__device__ float g_gin[Ss * Bb * 4 * Hh];        // precomputed input gates, [S,B,4H]
__device__ float g_wht[Hh * 4 * Hh];             // W_hh[l] transposed -> [K=1024, N=4096]
__device__ float g_c[Bb * Hh];                   // cell state
__device__ float g_hid[Bb * Ss * Ee];            // fc1 output, [B,S,E]

__device__ __forceinline__ float sigmoidf_(float x) { return 1.0f / (1.0f + expf(-x)); }

// ---------------- layer norm over seq dim ----------------
__global__ void ln_kernel(const float* __restrict__ fixp, float* __restrict__ fp) {
    __shared__ float red[256];
    int b = blockIdx.x, s = threadIdx.x;
    float v = fixp[b * Ss + s];
    red[s] = v;
    __syncthreads();
    for (int o = 128; o > 0; o >>= 1) { if (s < o) red[s] += red[s + o]; __syncthreads(); }
    float mu = red[0] * (1.0f / Ss);
    __syncthreads();
    float d = v - mu;
    red[s] = d * d;
    __syncthreads();
    for (int o = 128; o > 0; o >>= 1) { if (s < o) red[s] += red[s + o]; __syncthreads(); }
    float var = red[0] * (1.0f / Ss);
    float y = d * rsqrtf(var + 1e-5f);
    fp[b * Ss + s] = (y + 1.96f) / 3.92f * 12.0f;
}

// ---------------- W_hh transpose: [4H,H] -> [H,4H] ----------------
__global__ void transpose_kernel(const float* __restrict__ in, float* __restrict__ out) {
    __shared__ float t[32][33];
    int n0 = blockIdx.x * 32, k0 = blockIdx.y * 32;
    int tx = threadIdx.x, ty = threadIdx.y;
    t[ty][tx] = in[(n0 + ty) * Hh + (k0 + tx)];
    __syncthreads();
    out[(size_t)(k0 + ty) * (4 * Hh) + (n0 + tx)] = t[tx][ty];
}

// ---------------- gated input blend ----------------
__global__ void ew_kernel(const float* __restrict__ x, const float* __restrict__ ix,
                          const float* __restrict__ fp, float* __restrict__ inp, int layer) {
    int idx = blockIdx.x * 256 + threadIdx.x;
    int sb = idx >> 10;
    int b = sb & 31;
    int s = sb >> 5;
    float alpha = (11.0f - fp[b * Ss + s]) * 0.25f - (float)layer;
    float mask = sigmoidf_(alpha);
    float gate = sigmoidf_(alpha + 1.0f) - mask;
    float xv = (layer == 0) ? 0.0f : x[idx];
    inp[idx] = xv * (1.0f - gate) + ix[idx] * gate;
}

// ---------------- generic SGEMM: C[M,N] = A_gathered[M,K] * B[N,K]^T (+bias, act) ----
// MODE 0: A row = m
// MODE 1: A = emb, row = src[b*S+s] with m = s*B+b   (input projection)
// MODE 2: A = x [S,B,H], logical row m = b*S+s reads physical row s*B+b  (fc1 reorder)
// ACT  1: tanh epilogue
template <int MODE, int ACT>
__global__ void __launch_bounds__(256) sgemm_kernel(
    const float* __restrict__ A, const float* __restrict__ Bm, float* __restrict__ C,
    const float* __restrict__ bias1, const float* __restrict__ bias2,
    int M, int N, int K, const int* __restrict__ src)
{
    __shared__ float As[8][128];
    __shared__ float Bs[8][128];
    int tid = threadIdx.x;
    int m0 = blockIdx.y * 128, n0 = blockIdx.x * 128;

    int lr = tid >> 1;            // 0..127 (tile row for loads)
    int kq = (tid & 1) * 4;       // 0 or 4

    int am = m0 + lr;
    long arow;
    if (MODE == 1)      { int b = am & 31;  int s = am >> 5; arow = src[b * Ss + s]; }
    else if (MODE == 2) { int s = am & 255; int b = am >> 8; arow = (long)s * Bb + b; }
    else                { arow = am; }
    const float* aptr = A + arow * (long)K + kq;

    int bn = n0 + lr;
    bool bok = (bn < N);
    const float* bptr = Bm + (long)bn * K + kq;

    int tx = tid & 15, ty = tid >> 4;

    float acc[8][8];
#pragma unroll
    for (int i = 0; i < 8; i++)
#pragma unroll
        for (int j = 0; j < 8; j++) acc[i][j] = 0.0f;

    int T = K / 8;
    float4 aR = *(const float4*)(aptr);
    float4 bR = bok ? *(const float4*)(bptr) : make_float4(0.f, 0.f, 0.f, 0.f);

    for (int t = 0; t < T; t++) {
        As[kq + 0][lr] = aR.x; As[kq + 1][lr] = aR.y; As[kq + 2][lr] = aR.z; As[kq + 3][lr] = aR.w;
        Bs[kq + 0][lr] = bR.x; Bs[kq + 1][lr] = bR.y; Bs[kq + 2][lr] = bR.z; Bs[kq + 3][lr] = bR.w;
        __syncthreads();
        if (t + 1 < T) {
            aR = *(const float4*)(aptr + (t + 1) * 8);
            bR = bok ? *(const float4*)(bptr + (t + 1) * 8) : make_float4(0.f, 0.f, 0.f, 0.f);
        }
#pragma unroll
        for (int k = 0; k < 8; k++) {
            float4 a0 = *(const float4*)&As[k][ty * 4];
            float4 a1 = *(const float4*)&As[k][64 + ty * 4];
            float4 b0 = *(const float4*)&Bs[k][tx * 4];
            float4 b1 = *(const float4*)&Bs[k][64 + tx * 4];
            float ar[8] = {a0.x, a0.y, a0.z, a0.w, a1.x, a1.y, a1.z, a1.w};
            float br[8] = {b0.x, b0.y, b0.z, b0.w, b1.x, b1.y, b1.z, b1.w};
#pragma unroll
            for (int i = 0; i < 8; i++)
#pragma unroll
                for (int j = 0; j < 8; j++)
                    acc[i][j] += ar[i] * br[j];
        }
        __syncthreads();
    }

#pragma unroll
    for (int i = 0; i < 8; i++) {
        int row = m0 + ((i < 4) ? (ty * 4 + i) : (64 + ty * 4 + (i - 4)));
#pragma unroll
        for (int jh = 0; jh < 2; jh++) {
            int col = n0 + (jh ? (64 + tx * 4) : (tx * 4));
            if (col < N) {
                float v0 = acc[i][jh * 4 + 0];
                float v1 = acc[i][jh * 4 + 1];
                float v2 = acc[i][jh * 4 + 2];
                float v3 = acc[i][jh * 4 + 3];
                if (bias1) { v0 += bias1[col]; v1 += bias1[col + 1]; v2 += bias1[col + 2]; v3 += bias1[col + 3]; }
                if (bias2) { v0 += bias2[col]; v1 += bias2[col + 1]; v2 += bias2[col + 2]; v3 += bias2[col + 3]; }
                if (ACT == 1) { v0 = tanhf(v0); v1 = tanhf(v1); v2 = tanhf(v2); v3 = tanhf(v3); }
                float4 v; v.x = v0; v.y = v1; v.z = v2; v.w = v3;
                *(float4*)(&C[(long)row * N + col]) = v;
            }
        }
    }
}

// ---------------- one LSTM time step ----------------
// grid 128 CTAs (8 hidden units each, all 32 batches), 256 threads = 32 b x 8 jj.
// h for this step is x[s-1] (or h0 at s==0); Wh is pre-transposed [K,4H].
#define STEP_SMEM ((32 * 1025 + 128 * 32) * 4)

__global__ void __launch_bounds__(256) lstm_step_kernel(
    const float* __restrict__ gin,   // [S,B,4H]
    const float* __restrict__ wht,   // [1024,4096]
    const float* __restrict__ fp,    // [B,S]
    const float* __restrict__ h0l,   // [B,H] (layer slice)
    const float* __restrict__ c0l,   // [B,H]
    float* __restrict__ x,           // [S,B,H]
    float* __restrict__ cst,         // [B,H]
    int s, int layer)
{
    extern __shared__ float sm[];
    float* hsm = sm;                 // [32][1025] padded
    float* wsm = sm + 32 * 1025;     // [128][32] = [kk][jj*4 + gate]

    int tid = threadIdx.x;
    const float* hsrc = (s == 0) ? h0l : (x + (long)(s - 1) * Bb * Hh);

    // stage full h (32 KB*4) into smem
    for (int i = tid; i < (Bb * Hh) / 4; i += 256) {
        float4 v = *(const float4*)(hsrc + i * 4);
        int b = (i * 4) >> 10;
        int k = (i * 4) & 1023;
        float* d = hsm + b * 1025 + k;
        d[0] = v.x; d[1] = v.y; d[2] = v.z; d[3] = v.w;
    }

    int b = tid >> 3, jj = tid & 7;
    int j0 = blockIdx.x * 8;
    int j = j0 + jj;

    float acc0, acc1, acc2, acc3;
    {
        long gbase = ((long)(s * Bb + b)) * 4096 + j;
        acc0 = gin[gbase];
        acc1 = gin[gbase + 1024];
        acc2 = gin[gbase + 2048];
        acc3 = gin[gbase + 3072];
    }
    __syncthreads();

    for (int kc = 0; kc < 8; kc++) {
        // stage W chunk [128 k][8 jj][4 gates]
        for (int i = tid; i < 128 * 32; i += 256) {
            int kk = i >> 5;
            int r = i & 31;
            int gate = r >> 3;
            int jw = r & 7;
            wsm[kk * 32 + jw * 4 + gate] =
                wht[(long)(kc * 128 + kk) * 4096 + gate * 1024 + j0 + jw];
        }
        __syncthreads();
        const float* hrow = hsm + b * 1025 + kc * 128;
#pragma unroll 8
        for (int kk = 0; kk < 128; kk++) {
            float a = hrow[kk];
            float4 w = *(const float4*)(wsm + kk * 32 + jj * 4);
            acc0 += a * w.x;
            acc1 += a * w.y;
            acc2 += a * w.z;
            acc3 += a * w.w;
        }
        __syncthreads();
    }

    float i_ = sigmoidf_(acc0);
    float f_ = sigmoidf_(acc1);
    float g_ = tanhf(acc2);
    float o_ = sigmoidf_(acc3);
    float c_old = (s == 0) ? c0l[b * Hh + j] : cst[b * Hh + j];
    float h_old = hsm[b * 1025 + j];
    float cn = f_ * c_old + i_ * g_;
    float hn = o_ * tanhf(cn);
    float m = sigmoidf_((11.0f - fp[b * Ss + s]) * 0.25f - (float)layer);
    cn = cn * (1.0f - m) + c_old * m;
    hn = hn * (1.0f - m) + h_old * m;
    cst[b * Hh + j] = cn;
    x[((long)(s * Bb + b)) * Hh + j] = hn;
}

// ---------------- launch ----------------
extern "C" void kernel_launch(void* const* d_in, const int* in_sizes, int n_in,
                              void* d_out, int out_size) {
    (void)in_sizes; (void)n_in; (void)out_size;
    const int*   src   = (const int*)  d_in[0];
    const float* fixp  = (const float*)d_in[1];
    const float* emb   = (const float*)d_in[2];
    const float* W_lin = (const float*)d_in[3];
    const float* b_lin = (const float*)d_in[4];
    const float* W_ih  = (const float*)d_in[5];
    const float* W_hh  = (const float*)d_in[6];
    const float* b_ih  = (const float*)d_in[7];
    const float* b_hh  = (const float*)d_in[8];
    const float* fc_W1 = (const float*)d_in[9];
    const float* fc_b1 = (const float*)d_in[10];
    const float* fc_W2 = (const float*)d_in[11];
    const float* fc_b2 = (const float*)d_in[12];
    const float* h0    = (const float*)d_in[13];
    const float* c0    = (const float*)d_in[14];
    float* out = (float*)d_out;

    float *fp, *inputx, *inp, *x, *gin, *wht, *cst, *hid;
    cudaGetSymbolAddress((void**)&fp,     g_fp);
    cudaGetSymbolAddress((void**)&inputx, g_inputx);
    cudaGetSymbolAddress((void**)&inp,    g_inp);
    cudaGetSymbolAddress((void**)&x,      g_x);
    cudaGetSymbolAddress((void**)&gin,    g_gin);
    cudaGetSymbolAddress((void**)&wht,    g_wht);
    cudaGetSymbolAddress((void**)&cst,    g_c);
    cudaGetSymbolAddress((void**)&hid,    g_hid);

    cudaFuncSetAttribute(lstm_step_kernel,
                         cudaFuncAttributeMaxDynamicSharedMemorySize, STEP_SMEM);

    // 1) layer norm of fix_pred
    ln_kernel<<<Bb, 256>>>(fixp, fp);

    // 2) input projection: input_x[s,b,:] = W_lin @ emb[src[b,s],:] + b_lin
    sgemm_kernel<1, 0><<<dim3(Hh / 128, (Ss * Bb) / 128), 256>>>(
        emb, W_lin, inputx, b_lin, nullptr, Ss * Bb, Hh, Ee, src);

    // 3) three LSTM layers
    for (int l = 0; l < Ll; l++) {
        transpose_kernel<<<dim3(4 * Hh / 32, Hh / 32), dim3(32, 32)>>>(
            W_hh + (long)l * 4 * Hh * Hh, wht);
        ew_kernel<<<(Ss * Bb * Hh) / 256, 256>>>(x, inputx, fp, inp, l);
        sgemm_kernel<0, 0><<<dim3(4 * Hh / 128, (Ss * Bb) / 128), 256>>>(
            inp, W_ih + (long)l * 4 * Hh * Hh, gin,
            b_ih + (long)l * 4 * Hh, b_hh + (long)l * 4 * Hh,
            Ss * Bb, 4 * Hh, Hh, nullptr);
        for (int s = 0; s < Ss; s++) {
            lstm_step_kernel<<<128, 256, STEP_SMEM>>>(
                gin, wht, fp, h0 + (long)l * Bb * Hh, c0 + (long)l * Bb * Hh,
                x, cst, s, l);
        }
    }

    // 4) fc1 with tanh (reorders [S,B,H] -> [B,S,E])
    sgemm_kernel<2, 1><<<dim3(Ee / 128, (Ss * Bb) / 128), 256>>>(
        x, fc_W1, hid, fc_b1, nullptr, Ss * Bb, Ee, Hh, nullptr);

    // 5) fc2 -> logits [B,S,V]
    sgemm_kernel<0, 0><<<dim3((Vv + 127) / 128, (Ss * Bb) / 128), 256>>>(
        hid, fc_W2, out, fc_b2, nullptr, Ss * Bb, Vv, Ee, nullptr);
}

// round 3
// speedup vs baseline: 1.3175x; 1.3175x over previous
#include <cuda_runtime.h>
#include <math.h>

#define Bb 32
#define Ss 256
#define Vv 10000
#define Ee 512
#define Hh 1024
#define Ll 3

// ---------------- scratch (static __device__ arrays; no allocation) ----------------
__device__ float g_fp[Bb * Ss];                  // layer-normed fix_pred, [B,S]
__device__ float g_inputx[Ss * Bb * Hh];         // input projection, [S,B,H]
__device__ float g_inp[Ss * Bb * Hh];            // gated layer input,  [S,B,H]
__device__ float g_x[Ss * Bb * Hh];              // layer output / h history, [S,B,H]
__device__ float g_gin[Ss * Bb * 4 * Hh];        // precomputed input gates, [S,B,4H]
__device__ float g_wht[Hh * 4 * Hh];             // W_hh[l] transposed -> [K=1024, N=4096]
__device__ float g_c[Bb * Hh];                   // cell state
__device__ float g_hid[Bb * Ss * Ee];            // fc1 output, [B,S,E]

__device__ __forceinline__ float sigmoidf_(float x) { return 1.0f / (1.0f + expf(-x)); }

// ---- packed f32x2 helpers (Blackwell FFMA2 path, PTX-only) ----
__device__ __forceinline__ unsigned long long splat2(float x) {
    unsigned long long r;
    asm("mov.b64 %0, {%1, %1};" : "=l"(r) : "f"(x));
    return r;
}
__device__ __forceinline__ unsigned long long pack2(float x, float y) {
    unsigned long long r;
    asm("mov.b64 %0, {%1, %2};" : "=l"(r) : "f"(x), "f"(y));
    return r;
}
__device__ __forceinline__ float2 unpack2(unsigned long long v) {
    float2 r;
    asm("mov.b64 {%0, %1}, %2;" : "=f"(r.x), "=f"(r.y) : "l"(v));
    return r;
}
__device__ __forceinline__ void fma2(unsigned long long& d,
                                     unsigned long long a, unsigned long long b) {
    asm("fma.rn.f32x2 %0, %1, %2, %0;" : "+l"(d) : "l"(a), "l"(b));
}

// ---------------- layer norm over seq dim ----------------
__global__ void ln_kernel(const float* __restrict__ fixp, float* __restrict__ fp) {
    __shared__ float red[256];
    int b = blockIdx.x, s = threadIdx.x;
    float v = fixp[b * Ss + s];
    red[s] = v;
    __syncthreads();
    for (int o = 128; o > 0; o >>= 1) { if (s < o) red[s] += red[s + o]; __syncthreads(); }
    float mu = red[0] * (1.0f / Ss);
    __syncthreads();
    float d = v - mu;
    red[s] = d * d;
    __syncthreads();
    for (int o = 128; o > 0; o >>= 1) { if (s < o) red[s] += red[s + o]; __syncthreads(); }
    float var = red[0] * (1.0f / Ss);
    float y = d * rsqrtf(var + 1e-5f);
    fp[b * Ss + s] = (y + 1.96f) / 3.92f * 12.0f;
}

// ---------------- W_hh transpose: [4H,H] -> [H,4H] ----------------
__global__ void transpose_kernel(const float* __restrict__ in, float* __restrict__ out) {
    __shared__ float t[32][33];
    int n0 = blockIdx.x * 32, k0 = blockIdx.y * 32;
    int tx = threadIdx.x, ty = threadIdx.y;
    t[ty][tx] = in[(n0 + ty) * Hh + (k0 + tx)];
    __syncthreads();
    out[(size_t)(k0 + ty) * (4 * Hh) + (n0 + tx)] = t[tx][ty];
}

// ---------------- gated input blend ----------------
__global__ void ew_kernel(const float* __restrict__ x, const float* __restrict__ ix,
                          const float* __restrict__ fp, float* __restrict__ inp, int layer) {
    int idx = blockIdx.x * 256 + threadIdx.x;
    int sb = idx >> 10;
    int b = sb & 31;
    int s = sb >> 5;
    float alpha = (11.0f - fp[b * Ss + s]) * 0.25f - (float)layer;
    float mask = sigmoidf_(alpha);
    float gate = sigmoidf_(alpha + 1.0f) - mask;
    float xv = (layer == 0) ? 0.0f : x[idx];
    inp[idx] = xv * (1.0f - gate) + ix[idx] * gate;
}

// ---------------- generic SGEMM: C[M,N] = A_gathered[M,K] * B[N,K]^T (+bias, act) ----
// MODE 0: A row = m
// MODE 1: A = emb, row = src[b*S+s] with m = s*B+b   (input projection)
// MODE 2: A = x [S,B,H], logical row m = b*S+s reads physical row s*B+b  (fc1 reorder)
// ACT  1: tanh epilogue
template <int MODE, int ACT>
__global__ void __launch_bounds__(256) sgemm_kernel(
    const float* __restrict__ A, const float* __restrict__ Bm, float* __restrict__ C,
    const float* __restrict__ bias1, const float* __restrict__ bias2,
    int M, int N, int K, const int* __restrict__ src)
{
    __shared__ float As[8][128];
    __shared__ float Bs[8][128];
    int tid = threadIdx.x;
    int m0 = blockIdx.y * 128, n0 = blockIdx.x * 128;

    int lr = tid >> 1;            // 0..127 (tile row for loads)
    int kq = (tid & 1) * 4;       // 0 or 4

    int am = m0 + lr;
    long arow;
    if (MODE == 1)      { int b = am & 31;  int s = am >> 5; arow = src[b * Ss + s]; }
    else if (MODE == 2) { int s = am & 255; int b = am >> 8; arow = (long)s * Bb + b; }
    else                { arow = am; }
    const float* aptr = A + arow * (long)K + kq;

    int bn = n0 + lr;
    bool bok = (bn < N);
    const float* bptr = Bm + (long)bn * K + kq;

    int tx = tid & 15, ty = tid >> 4;

    // packed accumulators: acc[i][jp] = f32x2 pair of output cols
    // jp 0: (tx*4+0, tx*4+1)  jp 1: (tx*4+2, tx*4+3)
    // jp 2: (64+tx*4+0, +1)   jp 3: (64+tx*4+2, +3)
    unsigned long long acc[8][4];
#pragma unroll
    for (int i = 0; i < 8; i++)
#pragma unroll
        for (int j = 0; j < 4; j++) acc[i][j] = 0ULL;

    int T = K / 8;
    float4 aR = *(const float4*)(aptr);
    float4 bR = bok ? *(const float4*)(bptr) : make_float4(0.f, 0.f, 0.f, 0.f);

    for (int t = 0; t < T; t++) {
        As[kq + 0][lr] = aR.x; As[kq + 1][lr] = aR.y; As[kq + 2][lr] = aR.z; As[kq + 3][lr] = aR.w;
        Bs[kq + 0][lr] = bR.x; Bs[kq + 1][lr] = bR.y; Bs[kq + 2][lr] = bR.z; Bs[kq + 3][lr] = bR.w;
        __syncthreads();
        if (t + 1 < T) {
            aR = *(const float4*)(aptr + (t + 1) * 8);
            bR = bok ? *(const float4*)(bptr + (t + 1) * 8) : make_float4(0.f, 0.f, 0.f, 0.f);
        }
#pragma unroll
        for (int k = 0; k < 8; k++) {
            float4 a0 = *(const float4*)&As[k][ty * 4];
            float4 a1 = *(const float4*)&As[k][64 + ty * 4];
            // B pairs come straight out of smem as packed f32x2 (16B aligned)
            ulonglong2 bp01 = *(const ulonglong2*)&Bs[k][tx * 4];
            ulonglong2 bp23 = *(const ulonglong2*)&Bs[k][64 + tx * 4];
            unsigned long long aa[8];
            aa[0] = splat2(a0.x); aa[1] = splat2(a0.y); aa[2] = splat2(a0.z); aa[3] = splat2(a0.w);
            aa[4] = splat2(a1.x); aa[5] = splat2(a1.y); aa[6] = splat2(a1.z); aa[7] = splat2(a1.w);
#pragma unroll
            for (int i = 0; i < 8; i++) {
                fma2(acc[i][0], aa[i], bp01.x);
                fma2(acc[i][1], aa[i], bp01.y);
                fma2(acc[i][2], aa[i], bp23.x);
                fma2(acc[i][3], aa[i], bp23.y);
            }
        }
        __syncthreads();
    }

#pragma unroll
    for (int i = 0; i < 8; i++) {
        int row = m0 + ((i < 4) ? (ty * 4 + i) : (64 + ty * 4 + (i - 4)));
#pragma unroll
        for (int jh = 0; jh < 2; jh++) {
            int col = n0 + (jh ? (64 + tx * 4) : (tx * 4));
            if (col < N) {
                float2 p0 = unpack2(acc[i][jh * 2 + 0]);
                float2 p1 = unpack2(acc[i][jh * 2 + 1]);
                float v0 = p0.x, v1 = p0.y, v2 = p1.x, v3 = p1.y;
                if (bias1) { v0 += bias1[col]; v1 += bias1[col + 1]; v2 += bias1[col + 2]; v3 += bias1[col + 3]; }
                if (bias2) { v0 += bias2[col]; v1 += bias2[col + 1]; v2 += bias2[col + 2]; v3 += bias2[col + 3]; }
                if (ACT == 1) { v0 = tanhf(v0); v1 = tanhf(v1); v2 = tanhf(v2); v3 = tanhf(v3); }
                float4 v; v.x = v0; v.y = v1; v.z = v2; v.w = v3;
                *(float4*)(&C[(long)row * N + col]) = v;
            }
        }
    }
}

// ---------------- one LSTM time step ----------------
// grid 128 CTAs (8 hidden units each, all 32 batches), 256 threads = 32 b x 8 jj.
// h for this step is x[s-1] (or h0 at s==0); Wh is pre-transposed [K,4H].
#define HPAD 1028  /* words; mult of 4 for float4, bank stride 4 -> 4 distinct rows/warp OK */
#define STEP_SMEM ((32 * HPAD + 128 * 32) * 4)

__global__ void __launch_bounds__(256) lstm_step_kernel(
    const float* __restrict__ gin,   // [S,B,4H]
    const float* __restrict__ wht,   // [1024,4096]
    const float* __restrict__ fp,    // [B,S]
    const float* __restrict__ h0l,   // [B,H] (layer slice)
    const float* __restrict__ c0l,   // [B,H]
    float* __restrict__ x,           // [S,B,H]
    float* __restrict__ cst,         // [B,H]
    int s, int layer)
{
    extern __shared__ float sm[];
    float* hsm = sm;                 // [32][HPAD]
    float* wsm = sm + 32 * HPAD;     // [128][32] = [kk][jj*4 + gate]

    int tid = threadIdx.x;
    const float* hsrc = (s == 0) ? h0l : (x + (long)(s - 1) * Bb * Hh);

    // stage full h (128 KB) into smem
    for (int i = tid; i < (Bb * Hh) / 4; i += 256) {
        float4 v = *(const float4*)(hsrc + i * 4);
        int b = (i * 4) >> 10;
        int k = (i * 4) & 1023;
        *(float4*)(hsm + b * HPAD + k) = v;
    }

    int b = tid >> 3, jj = tid & 7;
    int j0 = blockIdx.x * 8;
    int j = j0 + jj;

    // packed accumulators: accA = (i, f) gates, accB = (g, o) gates
    unsigned long long accA, accB;
    {
        long gbase = ((long)(s * Bb + b)) * 4096 + j;
        accA = pack2(gin[gbase],        gin[gbase + 1024]);
        accB = pack2(gin[gbase + 2048], gin[gbase + 3072]);
    }
    __syncthreads();

    for (int kc = 0; kc < 8; kc++) {
        // stage W chunk [128 k][8 jj][4 gates]
        for (int i = tid; i < 128 * 32; i += 256) {
            int kk = i >> 5;
            int r = i & 31;
            int gate = r >> 3;
            int jw = r & 7;
            wsm[kk * 32 + jw * 4 + gate] =
                wht[(long)(kc * 128 + kk) * 4096 + gate * 1024 + j0 + jw];
        }
        __syncthreads();
        const float* hrow = hsm + b * HPAD + kc * 128;
#pragma unroll 8
        for (int k4 = 0; k4 < 32; k4++) {
            float4 hv = *(const float4*)(hrow + k4 * 4);
            const unsigned long long* wb =
                (const unsigned long long*)(wsm + (k4 * 4) * 32 + jj * 4);
            unsigned long long ha;
            ha = splat2(hv.x);
            fma2(accA, ha, wb[0]);  fma2(accB, ha, wb[1]);
            ha = splat2(hv.y);
            fma2(accA, ha, wb[16]); fma2(accB, ha, wb[17]);
            ha = splat2(hv.z);
            fma2(accA, ha, wb[32]); fma2(accB, ha, wb[33]);
            ha = splat2(hv.w);
            fma2(accA, ha, wb[48]); fma2(accB, ha, wb[49]);
        }
        __syncthreads();
    }

    float2 pA = unpack2(accA);
    float2 pB = unpack2(accB);
    float i_ = sigmoidf_(pA.x);
    float f_ = sigmoidf_(pA.y);
    float g_ = tanhf(pB.x);
    float o_ = sigmoidf_(pB.y);
    float c_old = (s == 0) ? c0l[b * Hh + j] : cst[b * Hh + j];
    float h_old = hsm[b * HPAD + j];
    float cn = f_ * c_old + i_ * g_;
    float hn = o_ * tanhf(cn);
    float m = sigmoidf_((11.0f - fp[b * Ss + s]) * 0.25f - (float)layer);
    cn = cn * (1.0f - m) + c_old * m;
    hn = hn * (1.0f - m) + h_old * m;
    cst[b * Hh + j] = cn;
    x[((long)(s * Bb + b)) * Hh + j] = hn;
}

// ---------------- launch ----------------
extern "C" void kernel_launch(void* const* d_in, const int* in_sizes, int n_in,
                              void* d_out, int out_size) {
    (void)in_sizes; (void)n_in; (void)out_size;
    const int*   src   = (const int*)  d_in[0];
    const float* fixp  = (const float*)d_in[1];
    const float* emb   = (const float*)d_in[2];
    const float* W_lin = (const float*)d_in[3];
    const float* b_lin = (const float*)d_in[4];
    const float* W_ih  = (const float*)d_in[5];
    const float* W_hh  = (const float*)d_in[6];
    const float* b_ih  = (const float*)d_in[7];
    const float* b_hh  = (const float*)d_in[8];
    const float* fc_W1 = (const float*)d_in[9];
    const float* fc_b1 = (const float*)d_in[10];
    const float* fc_W2 = (const float*)d_in[11];
    const float* fc_b2 = (const float*)d_in[12];
    const float* h0    = (const float*)d_in[13];
    const float* c0    = (const float*)d_in[14];
    float* out = (float*)d_out;

    float *fp, *inputx, *inp, *x, *gin, *wht, *cst, *hid;
    cudaGetSymbolAddress((void**)&fp,     g_fp);
    cudaGetSymbolAddress((void**)&inputx, g_inputx);
    cudaGetSymbolAddress((void**)&inp,    g_inp);
    cudaGetSymbolAddress((void**)&x,      g_x);
    cudaGetSymbolAddress((void**)&gin,    g_gin);
    cudaGetSymbolAddress((void**)&wht,    g_wht);
    cudaGetSymbolAddress((void**)&cst,    g_c);
    cudaGetSymbolAddress((void**)&hid,    g_hid);

    cudaFuncSetAttribute(lstm_step_kernel,
                         cudaFuncAttributeMaxDynamicSharedMemorySize, STEP_SMEM);

    // 1) layer norm of fix_pred
    ln_kernel<<<Bb, 256>>>(fixp, fp);

    // 2) input projection: input_x[s,b,:] = W_lin @ emb[src[b,s],:] + b_lin
    sgemm_kernel<1, 0><<<dim3(Hh / 128, (Ss * Bb) / 128), 256>>>(
        emb, W_lin, inputx, b_lin, nullptr, Ss * Bb, Hh, Ee, src);

    // 3) three LSTM layers
    for (int l = 0; l < Ll; l++) {
        transpose_kernel<<<dim3(4 * Hh / 32, Hh / 32), dim3(32, 32)>>>(
            W_hh + (long)l * 4 * Hh * Hh, wht);
        ew_kernel<<<(Ss * Bb * Hh) / 256, 256>>>(x, inputx, fp, inp, l);
        sgemm_kernel<0, 0><<<dim3(4 * Hh / 128, (Ss * Bb) / 128), 256>>>(
            inp, W_ih + (long)l * 4 * Hh * Hh, gin,
            b_ih + (long)l * 4 * Hh, b_hh + (long)l * 4 * Hh,
            Ss * Bb, 4 * Hh, Hh, nullptr);
        for (int s = 0; s < Ss; s++) {
            lstm_step_kernel<<<128, 256, STEP_SMEM>>>(
                gin, wht, fp, h0 + (long)l * Bb * Hh, c0 + (long)l * Bb * Hh,
                x, cst, s, l);
        }
    }

    // 4) fc1 with tanh (reorders [S,B,H] -> [B,S,E])
    sgemm_kernel<2, 1><<<dim3(Ee / 128, (Ss * Bb) / 128), 256>>>(
        x, fc_W1, hid, fc_b1, nullptr, Ss * Bb, Ee, Hh, nullptr);

    // 5) fc2 -> logits [B,S,V]
    sgemm_kernel<0, 0><<<dim3((Vv + 127) / 128, (Ss * Bb) / 128), 256>>>(
        hid, fc_W2, out, fc_b2, nullptr, Ss * Bb, Vv, Ee, nullptr);
}